// round 1
// baseline (speedup 1.0000x reference)
#include <cuda_runtime.h>
#include <math.h>

#define NROWS 8192
#define DDIM  64
#define KSIZE 128.0
#define SIGMA 3.0
#define EPSV  1e-5

// Scratch (no device allocation allowed in kernel_launch)
__device__ double g_sums[6];
__device__ float  g_sq[3 * NROWS];

// ---------------------------------------------------------------------------
// Zero accumulators (must happen every launch: graph replays)
// ---------------------------------------------------------------------------
__global__ void init_kernel() {
    int t = threadIdx.x;
    if (t < 6) g_sums[t] = 0.0;
}

// ---------------------------------------------------------------------------
// Squared row norms for all 3 modalities: warp per row
// ---------------------------------------------------------------------------
__global__ void sqnorm_kernel(const float* __restrict__ m0,
                              const float* __restrict__ m1,
                              const float* __restrict__ m2) {
    int warp = (blockIdx.x * blockDim.x + threadIdx.x) >> 5;
    int lane = threadIdx.x & 31;
    if (warp >= 3 * NROWS) return;
    int mod = warp / NROWS;
    int row = warp - mod * NROWS;
    const float* p = (mod == 0) ? m0 : (mod == 1) ? m1 : m2;
    float2 v = ((const float2*)(p + (size_t)row * DDIM))[lane];
    float s = v.x * v.x + v.y * v.y;
    #pragma unroll
    for (int off = 16; off > 0; off >>= 1)
        s += __shfl_down_sync(0xffffffffu, s, off);
    if (lane == 0) g_sq[warp] = s;
}

// ---------------------------------------------------------------------------
// Main: per (pair, tile-i, tile-j) block computes 64x64 kernel-matrix sums.
// Symmetric pairs (z<3) only do upper-triangular tiles, off-diag weighted 2x.
// ---------------------------------------------------------------------------
__global__ __launch_bounds__(256) void gram_kernel(const float* __restrict__ m0,
                                                   const float* __restrict__ m1,
                                                   const float* __restrict__ m2) {
    const int pz = blockIdx.z;
    const int pa_[6] = {0, 1, 2, 0, 0, 1};
    const int pb_[6] = {0, 1, 2, 1, 2, 2};
    const int ia = pa_[pz], ib = pb_[pz];
    const bool sym = (pz < 3);
    const int bi = blockIdx.y, bj = blockIdx.x;
    if (sym && bj < bi) return;
    const float w = (sym && bj > bi) ? 2.0f : 1.0f;

    const float* A = (ia == 0) ? m0 : (ia == 1) ? m1 : m2;
    const float* B = (ib == 0) ? m0 : (ib == 1) ? m1 : m2;

    // Transposed tiles: As[k*64 + m] = A[(bi*64+m)*64 + k]
    __shared__ float As[64 * 64];
    __shared__ float Bs[64 * 64];

    const int tid  = threadIdx.x;
    const int dgrp = (tid & 15) * 4;   // k base (0..60 step 4)
    const int r0   = tid >> 4;         // 0..15

    #pragma unroll
    for (int rr = 0; rr < 64; rr += 16) {
        const int m = r0 + rr;
        float4 va = *(const float4*)(A + ((size_t)(bi * 64 + m)) * DDIM + dgrp);
        float4 vb = *(const float4*)(B + ((size_t)(bj * 64 + m)) * DDIM + dgrp);
        As[(dgrp + 0) * 64 + m] = va.x;
        As[(dgrp + 1) * 64 + m] = va.y;
        As[(dgrp + 2) * 64 + m] = va.z;
        As[(dgrp + 3) * 64 + m] = va.w;
        Bs[(dgrp + 0) * 64 + m] = vb.x;
        Bs[(dgrp + 1) * 64 + m] = vb.y;
        Bs[(dgrp + 2) * 64 + m] = vb.z;
        Bs[(dgrp + 3) * 64 + m] = vb.w;
    }
    __syncthreads();

    const int tx = tid & 15;   // n direction
    const int ty = tid >> 4;   // m direction

    float acc[4][4];
    #pragma unroll
    for (int i = 0; i < 4; i++)
        #pragma unroll
        for (int j = 0; j < 4; j++) acc[i][j] = 0.0f;

    const float4* As4 = (const float4*)As;
    const float4* Bs4 = (const float4*)Bs;

    #pragma unroll 16
    for (int k = 0; k < 64; k++) {
        float4 a = As4[k * 16 + ty];
        float4 b = Bs4[k * 16 + tx];
        acc[0][0] += a.x * b.x; acc[0][1] += a.x * b.y; acc[0][2] += a.x * b.z; acc[0][3] += a.x * b.w;
        acc[1][0] += a.y * b.x; acc[1][1] += a.y * b.y; acc[1][2] += a.y * b.z; acc[1][3] += a.y * b.w;
        acc[2][0] += a.z * b.x; acc[2][1] += a.z * b.y; acc[2][2] += a.z * b.z; acc[2][3] += a.z * b.w;
        acc[3][0] += a.w * b.x; acc[3][1] += a.w * b.y; acc[3][2] += a.w * b.z; acc[3][3] += a.w * b.w;
    }

    const float* sqA = g_sq + ia * NROWS;
    const float* sqB = g_sq + ib * NROWS;
    float sa[4], sb[4];
    #pragma unroll
    for (int i = 0; i < 4; i++) sa[i] = sqA[bi * 64 + ty * 4 + i];
    #pragma unroll
    for (int j = 0; j < 4; j++) sb[j] = sqB[bj * 64 + tx * 4 + j];

    const float scale = (float)(1.0 / KSIZE);
    float s = 0.0f;
    #pragma unroll
    for (int i = 0; i < 4; i++)
        #pragma unroll
        for (int j = 0; j < 4; j++)
            s += __expf((2.0f * acc[i][j] - sa[i] - sb[j]) * scale);

    // block reduction
    #pragma unroll
    for (int off = 16; off > 0; off >>= 1)
        s += __shfl_down_sync(0xffffffffu, s, off);
    __shared__ float red[8];
    const int lane = tid & 31, warp = tid >> 5;
    if (lane == 0) red[warp] = s;
    __syncthreads();
    if (tid == 0) {
        float bs = 0.0f;
        #pragma unroll
        for (int q = 0; q < 8; q++) bs += red[q];
        atomicAdd(&g_sums[pz], (double)(bs * w));
    }
}

// ---------------------------------------------------------------------------
// Epilogue: 3 log-ratio terms in double, write float scalar
// ---------------------------------------------------------------------------
__global__ void finish_kernel(float* __restrict__ out) {
    const double norm = sqrt(2.0 * M_PI * KSIZE);
    const double inv  = 1.0 / ((double)NROWS * (double)NROWS * norm);
    double m[6];
    #pragma unroll
    for (int q = 0; q < 6; q++) m[q] = g_sums[q] * inv;
    // m[0]=m00 m[1]=m11 m[2]=m22 m[3]=m01 m[4]=m02 m[5]=m12
    double loss = 0.0;
    loss += log(SIGMA * sqrt(m[0] * m[1] + EPSV) / (m[3] + EPSV));
    loss += log(SIGMA * sqrt(m[0] * m[2] + EPSV) / (m[4] + EPSV));
    loss += log(SIGMA * sqrt(m[1] * m[2] + EPSV) / (m[5] + EPSV));
    out[0] = (float)loss;
}

// ---------------------------------------------------------------------------
extern "C" void kernel_launch(void* const* d_in, const int* in_sizes, int n_in,
                              void* d_out, int out_size) {
    const float* m0 = (const float*)d_in[0];
    const float* m1 = (const float*)d_in[1];
    const float* m2 = (const float*)d_in[2];
    float* out = (float*)d_out;

    init_kernel<<<1, 32>>>();
    sqnorm_kernel<<<(3 * NROWS * 32 + 255) / 256, 256>>>(m0, m1, m2);
    dim3 grid(NROWS / 64, NROWS / 64, 6);
    gram_kernel<<<grid, 256>>>(m0, m1, m2);
    finish_kernel<<<1, 1>>>(out);
}

// round 3
// speedup vs baseline: 10.2885x; 10.2885x over previous
#include <cuda_runtime.h>
#include <cuda_bf16.h>
#include <math.h>
#include <stdint.h>

#define NROWS 8192
#define DDIM  64
#define KSIZE 128.0
#define SIGMA 3.0
#define EPSV  1e-5

// ---------------------------------------------------------------------------
// Device-global scratch (no allocation allowed in kernel_launch)
// ---------------------------------------------------------------------------
__device__ double g_sums[6];
__device__ float  g_rl[3 * NROWS];                              // -|x|^2/(128 ln2)
__device__ __align__(16) __nv_bfloat16 g_bf[3 * NROWS * DDIM];  // bf16 copies

// ---------------------------------------------------------------------------
static __device__ __forceinline__ uint32_t smem_u32(const void* p) {
    uint32_t a;
    asm("{ .reg .u64 t; cvta.to.shared.u64 t, %1; cvt.u32.u64 %0, t; }"
        : "=r"(a) : "l"(p));
    return a;
}
static __device__ __forceinline__ float ex2f(float x) {
    float r; asm("ex2.approx.ftz.f32 %0, %1;" : "=f"(r) : "f"(x)); return r;
}
static __device__ __forceinline__ void ldsm_x4(uint32_t* r, uint32_t addr) {
    asm volatile("ldmatrix.sync.aligned.m8n8.x4.shared.b16 {%0,%1,%2,%3}, [%4];"
                 : "=r"(r[0]), "=r"(r[1]), "=r"(r[2]), "=r"(r[3]) : "r"(addr));
}
static __device__ __forceinline__ void mma16816(float* d, const uint32_t* a,
                                                uint32_t b0, uint32_t b1) {
    asm volatile(
        "mma.sync.aligned.m16n8k16.row.col.f32.bf16.bf16.f32 "
        "{%0,%1,%2,%3}, {%4,%5,%6,%7}, {%8,%9}, {%0,%1,%2,%3};"
        : "+f"(d[0]), "+f"(d[1]), "+f"(d[2]), "+f"(d[3])
        : "r"(a[0]), "r"(a[1]), "r"(a[2]), "r"(a[3]), "r"(b0), "r"(b1));
}

// ---------------------------------------------------------------------------
// Aux kernels
// ---------------------------------------------------------------------------
__global__ void init_kernel() {
    if (threadIdx.x < 6) g_sums[threadIdx.x] = 0.0;
}

// fp32 -> bf16 conversion of all three inputs
__global__ void prep_kernel(const float* __restrict__ m0,
                            const float* __restrict__ m1,
                            const float* __restrict__ m2) {
    int i = blockIdx.x * blockDim.x + threadIdx.x;   // over NROWS*DDIM/4
    int mod = blockIdx.y;
    const float* src = (mod == 0) ? m0 : (mod == 1) ? m1 : m2;
    float4 v = ((const float4*)src)[i];
    __nv_bfloat162* dst = (__nv_bfloat162*)(g_bf + (size_t)mod * NROWS * DDIM);
    dst[2 * i]     = __float22bfloat162_rn(make_float2(v.x, v.y));
    dst[2 * i + 1] = __float22bfloat162_rn(make_float2(v.z, v.w));
}

// fp32 row norms in log2 units: rl = -|x|^2 / (128*ln2)
__global__ void sqnorm_kernel(const float* __restrict__ m0,
                              const float* __restrict__ m1,
                              const float* __restrict__ m2) {
    int warp = (blockIdx.x * blockDim.x + threadIdx.x) >> 5;
    int lane = threadIdx.x & 31;
    if (warp >= 3 * NROWS) return;
    int mod = warp / NROWS;
    int row = warp - mod * NROWS;
    const float* p = (mod == 0) ? m0 : (mod == 1) ? m1 : m2;
    float2 v = ((const float2*)(p + (size_t)row * DDIM))[lane];
    float s = v.x * v.x + v.y * v.y;
    #pragma unroll
    for (int off = 16; off > 0; off >>= 1)
        s += __shfl_down_sync(0xffffffffu, s, off);
    if (lane == 0) g_rl[warp] = s * (float)(-1.0 / (128.0 * M_LN2));
}

// ---------------------------------------------------------------------------
// Main Gram kernel: CTA tile 128x128, K=64, mma.sync m16n8k16 bf16.
// grid = (64, 64, 6): bj, bi, pair. Symmetric pairs use bj>=bi tiles,
// off-diagonal tiles weighted x2 (folded as +1.0 in the log2 exponent).
// ---------------------------------------------------------------------------
__global__ __launch_bounds__(256, 2) void gram_mma() {
    const int pz = blockIdx.z;
    const int pa_[6] = {0, 1, 2, 0, 0, 1};
    const int pb_[6] = {0, 1, 2, 1, 2, 2};
    const int ia = pa_[pz], ib = pb_[pz];
    const int bi = blockIdx.y, bj = blockIdx.x;
    if (pz < 3 && bj < bi) return;
    const float lw = (pz < 3 && bj > bi) ? 1.0f : 0.0f;   // log2(weight)

    // Swizzled tiles: row r, 16B chunk kc stored at chunk index (kc ^ (r&7))
    __shared__ __align__(128) uint4 smA[1024];   // 128 rows x 8 chunks
    __shared__ __align__(128) uint4 smB[1024];
    __shared__ float red[8];

    const int tid = threadIdx.x;
    const int wid = tid >> 5, lane = tid & 31;

    const uint4* Ag = (const uint4*)(g_bf + (size_t)ia * NROWS * DDIM) + (size_t)bi * 1024;
    const uint4* Bg = (const uint4*)(g_bf + (size_t)ib * NROWS * DDIM) + (size_t)bj * 1024;
    #pragma unroll
    for (int c = tid; c < 1024; c += 256) {
        int row = c >> 3, kc = c & 7;
        smA[row * 8 + (kc ^ (row & 7))] = Ag[c];
        smB[row * 8 + (kc ^ (row & 7))] = Bg[c];
    }
    __syncthreads();

    const int warp_m = (wid & 1) * 64;     // 2 warp-rows
    const int warp_n = (wid >> 1) * 32;    // 4 warp-cols
    const uint32_t baseA = smem_u32(smA);
    const uint32_t baseB = smem_u32(smB);

    float d[4][4][4];
    #pragma unroll
    for (int mf = 0; mf < 4; mf++)
        #pragma unroll
        for (int nf = 0; nf < 4; nf++)
            #pragma unroll
            for (int q = 0; q < 4; q++) d[mf][nf][q] = 0.0f;

    // ldmatrix lane->row mapping precompute
    const int a_r = (lane & 15);           // row within 16-row frag
    const int a_kh = lane >> 4;            // k-half select (0/1)
    const int b_r = (lane & 7) + ((lane & 16) >> 1);  // row within 16-row pair
    const int b_kh = (lane >> 3) & 1;

    #pragma unroll
    for (int ks = 0; ks < 4; ks++) {
        uint32_t a[4][4];
        #pragma unroll
        for (int mf = 0; mf < 4; mf++) {
            int row = warp_m + mf * 16 + a_r;
            int kc = ks * 2 + a_kh;
            ldsm_x4(a[mf], baseA + row * 128 + ((kc ^ (row & 7)) << 4));
        }
        uint32_t b[2][4];
        #pragma unroll
        for (int bf = 0; bf < 2; bf++) {
            int row = warp_n + bf * 16 + b_r;
            int kc = ks * 2 + b_kh;
            ldsm_x4(b[bf], baseB + row * 128 + ((kc ^ (row & 7)) << 4));
        }
        #pragma unroll
        for (int mf = 0; mf < 4; mf++)
            #pragma unroll
            for (int nf = 0; nf < 4; nf++)
                mma16816(d[mf][nf], a[mf],
                         b[nf >> 1][(nf & 1) * 2], b[nf >> 1][(nf & 1) * 2 + 1]);
    }

    // Epilogue: K(i,j) = 2^( d*C2 + rl_a[i] + rl_b[j] + lw )
    const int g = lane >> 2, tig = lane & 3;
    const float C2 = (float)(1.0 / (64.0 * M_LN2));

    float ra[4][2], rb[4][2];
    const float* rlA = g_rl + ia * NROWS + bi * 128 + warp_m;
    const float* rlB = g_rl + ib * NROWS + bj * 128 + warp_n;
    #pragma unroll
    for (int mf = 0; mf < 4; mf++) {
        ra[mf][0] = rlA[mf * 16 + g];
        ra[mf][1] = rlA[mf * 16 + g + 8];
    }
    #pragma unroll
    for (int nf = 0; nf < 4; nf++) {
        rb[nf][0] = rlB[nf * 8 + tig * 2] + lw;
        rb[nf][1] = rlB[nf * 8 + tig * 2 + 1] + lw;
    }

    float s = 0.0f;
    #pragma unroll
    for (int mf = 0; mf < 4; mf++)
        #pragma unroll
        for (int nf = 0; nf < 4; nf++) {
            s += ex2f(fmaf(d[mf][nf][0], C2, ra[mf][0] + rb[nf][0]));
            s += ex2f(fmaf(d[mf][nf][1], C2, ra[mf][0] + rb[nf][1]));
            s += ex2f(fmaf(d[mf][nf][2], C2, ra[mf][1] + rb[nf][0]));
            s += ex2f(fmaf(d[mf][nf][3], C2, ra[mf][1] + rb[nf][1]));
        }

    // Block reduce -> one double atomic per block
    #pragma unroll
    for (int off = 16; off > 0; off >>= 1)
        s += __shfl_down_sync(0xffffffffu, s, off);
    if (lane == 0) red[wid] = s;
    __syncthreads();
    if (tid == 0) {
        float bs = 0.0f;
        #pragma unroll
        for (int q = 0; q < 8; q++) bs += red[q];
        atomicAdd(&g_sums[pz], (double)bs);
    }
}

// ---------------------------------------------------------------------------
// Epilogue: 3 log-ratio terms in double
// ---------------------------------------------------------------------------
__global__ void finish_kernel(float* __restrict__ out) {
    const double norm = sqrt(2.0 * M_PI * KSIZE);
    const double inv  = 1.0 / ((double)NROWS * (double)NROWS * norm);
    double m[6];
    #pragma unroll
    for (int q = 0; q < 6; q++) m[q] = g_sums[q] * inv;
    double loss = 0.0;
    loss += log(SIGMA * sqrt(m[0] * m[1] + EPSV) / (m[3] + EPSV));
    loss += log(SIGMA * sqrt(m[0] * m[2] + EPSV) / (m[4] + EPSV));
    loss += log(SIGMA * sqrt(m[1] * m[2] + EPSV) / (m[5] + EPSV));
    out[0] = (float)loss;
}

// ---------------------------------------------------------------------------
extern "C" void kernel_launch(void* const* d_in, const int* in_sizes, int n_in,
                              void* d_out, int out_size) {
    const float* m0 = (const float*)d_in[0];
    const float* m1 = (const float*)d_in[1];
    const float* m2 = (const float*)d_in[2];
    float* out = (float*)d_out;

    init_kernel<<<1, 32>>>();
    prep_kernel<<<dim3(NROWS * DDIM / 4 / 256, 3), 256>>>(m0, m1, m2);
    sqnorm_kernel<<<(3 * NROWS * 32) / 256, 256>>>(m0, m1, m2);
    gram_mma<<<dim3(64, 64, 6), 256>>>();
    finish_kernel<<<1, 1>>>(out);
}

// round 4
// speedup vs baseline: 11.7784x; 1.1448x over previous
#include <cuda_runtime.h>
#include <cuda_bf16.h>
#include <math.h>
#include <stdint.h>

#define NROWS 8192
#define DDIM  64
#define KSIZE 128.0
#define SIGMA 3.0
#define EPSV  1e-5

// ---------------------------------------------------------------------------
// Device-global scratch (no allocation allowed in kernel_launch)
// ---------------------------------------------------------------------------
__device__ double g_sums[6];
__device__ float  g_rl[3 * NROWS];                              // -|x|^2/(128 ln2)
__device__ __align__(16) __nv_bfloat16 g_bf[3 * NROWS * DDIM];  // bf16 copies

// ---------------------------------------------------------------------------
static __device__ __forceinline__ uint32_t smem_u32(const void* p) {
    uint32_t a;
    asm("{ .reg .u64 t; cvta.to.shared.u64 t, %1; cvt.u32.u64 %0, t; }"
        : "=r"(a) : "l"(p));
    return a;
}
static __device__ __forceinline__ float ex2f(float x) {
    float r; asm("ex2.approx.ftz.f32 %0, %1;" : "=f"(r) : "f"(x)); return r;
}
static __device__ __forceinline__ void ldsm_x4(uint32_t* r, uint32_t addr) {
    asm volatile("ldmatrix.sync.aligned.m8n8.x4.shared.b16 {%0,%1,%2,%3}, [%4];"
                 : "=r"(r[0]), "=r"(r[1]), "=r"(r[2]), "=r"(r[3]) : "r"(addr));
}
static __device__ __forceinline__ void mma16816(float* d, const uint32_t* a,
                                                uint32_t b0, uint32_t b1) {
    asm volatile(
        "mma.sync.aligned.m16n8k16.row.col.f32.bf16.bf16.f32 "
        "{%0,%1,%2,%3}, {%4,%5,%6,%7}, {%8,%9}, {%0,%1,%2,%3};"
        : "+f"(d[0]), "+f"(d[1]), "+f"(d[2]), "+f"(d[3])
        : "r"(a[0]), "r"(a[1]), "r"(a[2]), "r"(a[3]), "r"(b0), "r"(b1));
}
static __device__ __forceinline__ void cp16(uint32_t dst, const void* src) {
    asm volatile("cp.async.cg.shared.global [%0], [%1], 16;" :: "r"(dst), "l"(src));
}
#define CP_COMMIT() asm volatile("cp.async.commit_group;" ::: "memory")
#define CP_WAIT(n)  asm volatile("cp.async.wait_group %0;" :: "n"(n) : "memory")

// ---------------------------------------------------------------------------
// Aux kernels
// ---------------------------------------------------------------------------
__global__ void init_kernel() {
    if (threadIdx.x < 6) g_sums[threadIdx.x] = 0.0;
}

__global__ void prep_kernel(const float* __restrict__ m0,
                            const float* __restrict__ m1,
                            const float* __restrict__ m2) {
    int i = blockIdx.x * blockDim.x + threadIdx.x;   // over NROWS*DDIM/4
    int mod = blockIdx.y;
    const float* src = (mod == 0) ? m0 : (mod == 1) ? m1 : m2;
    float4 v = ((const float4*)src)[i];
    __nv_bfloat162* dst = (__nv_bfloat162*)(g_bf + (size_t)mod * NROWS * DDIM);
    dst[2 * i]     = __float22bfloat162_rn(make_float2(v.x, v.y));
    dst[2 * i + 1] = __float22bfloat162_rn(make_float2(v.z, v.w));
}

__global__ void sqnorm_kernel(const float* __restrict__ m0,
                              const float* __restrict__ m1,
                              const float* __restrict__ m2) {
    int warp = (blockIdx.x * blockDim.x + threadIdx.x) >> 5;
    int lane = threadIdx.x & 31;
    if (warp >= 3 * NROWS) return;
    int mod = warp / NROWS;
    int row = warp - mod * NROWS;
    const float* p = (mod == 0) ? m0 : (mod == 1) ? m1 : m2;
    float2 v = ((const float2*)(p + (size_t)row * DDIM))[lane];
    float s = v.x * v.x + v.y * v.y;
    #pragma unroll
    for (int off = 16; off > 0; off >>= 1)
        s += __shfl_down_sync(0xffffffffu, s, off);
    if (lane == 0) g_rl[warp] = s * (float)(-1.0 / (128.0 * M_LN2));
}

// ---------------------------------------------------------------------------
// One 128x128 tile: MMA over K=64 from swizzled smem + exp epilogue.
// Returns this thread's partial kernel-sum.
// ---------------------------------------------------------------------------
static __device__ __forceinline__ float tile_compute(
    uint32_t baseA, uint32_t baseB, const float* ra,
    const float* __restrict__ rlB, float lw,
    int lane, int warp_m, int warp_n)
{
    const int tig = lane & 3;
    const int a_r  = lane & 15;
    const int a_kh = lane >> 4;
    const int b_r  = (lane & 7) + ((lane & 16) >> 1);
    const int b_kh = (lane >> 3) & 1;

    float d[4][4][4];
    #pragma unroll
    for (int mf = 0; mf < 4; mf++)
        #pragma unroll
        for (int nf = 0; nf < 4; nf++)
            #pragma unroll
            for (int q = 0; q < 4; q++) d[mf][nf][q] = 0.0f;

    #pragma unroll
    for (int ks = 0; ks < 4; ks++) {
        uint32_t a[4][4];
        #pragma unroll
        for (int mf = 0; mf < 4; mf++) {
            int row = warp_m + mf * 16 + a_r;
            int kc = ks * 2 + a_kh;
            ldsm_x4(a[mf], baseA + row * 128 + ((kc ^ (row & 7)) << 4));
        }
        uint32_t b[2][4];
        #pragma unroll
        for (int bf = 0; bf < 2; bf++) {
            int row = warp_n + bf * 16 + b_r;
            int kc = ks * 2 + b_kh;
            ldsm_x4(b[bf], baseB + row * 128 + ((kc ^ (row & 7)) << 4));
        }
        #pragma unroll
        for (int mf = 0; mf < 4; mf++)
            #pragma unroll
            for (int nf = 0; nf < 4; nf++)
                mma16816(d[mf][nf], a[mf],
                         b[nf >> 1][(nf & 1) * 2], b[nf >> 1][(nf & 1) * 2 + 1]);
    }

    // pb[nf][qn] = 2^(rb + lw); K(i,j) = 2^(d*C2 + ra) * pb
    const float C2 = (float)(1.0 / (64.0 * M_LN2));
    float pb[4][2];
    #pragma unroll
    for (int nf = 0; nf < 4; nf++) {
        pb[nf][0] = ex2f(rlB[nf * 8 + tig * 2] + lw);
        pb[nf][1] = ex2f(rlB[nf * 8 + tig * 2 + 1] + lw);
    }

    float s0 = 0.0f, s1 = 0.0f, s2 = 0.0f, s3 = 0.0f;
    #pragma unroll
    for (int mf = 0; mf < 4; mf++)
        #pragma unroll
        for (int nf = 0; nf < 4; nf++) {
            s0 = fmaf(ex2f(fmaf(d[mf][nf][0], C2, ra[2 * mf])),     pb[nf][0], s0);
            s1 = fmaf(ex2f(fmaf(d[mf][nf][1], C2, ra[2 * mf])),     pb[nf][1], s1);
            s2 = fmaf(ex2f(fmaf(d[mf][nf][2], C2, ra[2 * mf + 1])), pb[nf][0], s2);
            s3 = fmaf(ex2f(fmaf(d[mf][nf][3], C2, ra[2 * mf + 1])), pb[nf][1], s3);
        }
    return (s0 + s1) + (s2 + s3);
}

// ---------------------------------------------------------------------------
// Main Gram kernel. grid = (32, 64, 6): bjs (256-col supertile), bi, pair.
// Each CTA: one 128-row A tile vs two 128-row B tiles (A reused, B double-
// buffered via cp.async). Symmetric pairs: sub-tile weights {0,1,2} folded
// into the exponent (lw = log2 w).
// ---------------------------------------------------------------------------
__global__ __launch_bounds__(256, 2) void gram_mma() {
    const int pz = blockIdx.z;
    const int pa_[6] = {0, 1, 2, 0, 0, 1};
    const int pb_[6] = {0, 1, 2, 1, 2, 2};
    const int ia = pa_[pz], ib = pb_[pz];
    const int bi = blockIdx.y, bjs = blockIdx.x;
    const int j0 = 2 * bjs, j1 = 2 * bjs + 1;
    const bool sym = (pz < 3);
    if (sym && j1 < bi) return;

    const bool do0 = !(sym && j0 < bi);
    const float lw0 = (sym && j0 > bi) ? 1.0f : 0.0f;
    const float lw1 = (sym && j1 > bi) ? 1.0f : 0.0f;

    __shared__ __align__(128) uint4 smA[1024];      // 16 KB
    __shared__ __align__(128) uint4 smB[2][1024];   // 32 KB

    const int tid = threadIdx.x;
    const int wid = tid >> 5, lane = tid & 31;

    const uint4* Ag = (const uint4*)(g_bf + (size_t)ia * NROWS * DDIM) + (size_t)bi * 1024;
    const uint4* Bbase = (const uint4*)(g_bf + (size_t)ib * NROWS * DDIM);
    const uint4* Bg0 = Bbase + (size_t)j0 * 1024;
    const uint4* Bg1 = Bbase + (size_t)j1 * 1024;

    const uint32_t baseA  = smem_u32(smA);
    const uint32_t baseB0 = smem_u32(smB[0]);
    const uint32_t baseB1 = smem_u32(smB[1]);

    // group 0: A + B0 ; group 1: B1
    #pragma unroll
    for (int q = 0; q < 4; q++) {
        int c = tid + 256 * q;
        int row = c >> 3, kc = c & 7;
        uint32_t sw = (uint32_t)(row * 8 + (kc ^ (row & 7))) * 16u;
        cp16(baseA + sw, Ag + c);
        if (do0) cp16(baseB0 + sw, Bg0 + c);
    }
    CP_COMMIT();
    #pragma unroll
    for (int q = 0; q < 4; q++) {
        int c = tid + 256 * q;
        int row = c >> 3, kc = c & 7;
        uint32_t sw = (uint32_t)(row * 8 + (kc ^ (row & 7))) * 16u;
        cp16(baseB1 + sw, Bg1 + c);
    }
    CP_COMMIT();

    // Per-thread A-row exponent terms (8 values)
    const int warp_m = (wid & 1) * 64;
    const int warp_n = (wid >> 1) * 32;
    const int g = lane >> 2;
    const float* rlA = g_rl + ia * NROWS + bi * 128 + warp_m;
    float ra[8];
    #pragma unroll
    for (int mf = 0; mf < 4; mf++) {
        ra[2 * mf]     = rlA[mf * 16 + g];
        ra[2 * mf + 1] = rlA[mf * 16 + g + 8];
    }

    float s = 0.0f;

    CP_WAIT(1);            // A + B0 resident
    __syncthreads();
    if (do0)
        s += tile_compute(baseA, baseB0, ra,
                          g_rl + ib * NROWS + j0 * 128 + warp_n, lw0,
                          lane, warp_m, warp_n);

    CP_WAIT(0);            // B1 resident
    __syncthreads();
    s += tile_compute(baseA, baseB1, ra,
                      g_rl + ib * NROWS + j1 * 128 + warp_n, lw1,
                      lane, warp_m, warp_n);

    // Warp reduce -> one double atomic per warp
    #pragma unroll
    for (int off = 16; off > 0; off >>= 1)
        s += __shfl_down_sync(0xffffffffu, s, off);
    if (lane == 0)
        atomicAdd(&g_sums[pz], (double)s);
}

// ---------------------------------------------------------------------------
// Epilogue: 3 log-ratio terms in double
// ---------------------------------------------------------------------------
__global__ void finish_kernel(float* __restrict__ out) {
    const double norm = sqrt(2.0 * M_PI * KSIZE);
    const double inv  = 1.0 / ((double)NROWS * (double)NROWS * norm);
    double m[6];
    #pragma unroll
    for (int q = 0; q < 6; q++) m[q] = g_sums[q] * inv;
    double loss = 0.0;
    loss += log(SIGMA * sqrt(m[0] * m[1] + EPSV) / (m[3] + EPSV));
    loss += log(SIGMA * sqrt(m[0] * m[2] + EPSV) / (m[4] + EPSV));
    loss += log(SIGMA * sqrt(m[1] * m[2] + EPSV) / (m[5] + EPSV));
    out[0] = (float)loss;
}

// ---------------------------------------------------------------------------
extern "C" void kernel_launch(void* const* d_in, const int* in_sizes, int n_in,
                              void* d_out, int out_size) {
    const float* m0 = (const float*)d_in[0];
    const float* m1 = (const float*)d_in[1];
    const float* m2 = (const float*)d_in[2];
    float* out = (float*)d_out;

    init_kernel<<<1, 32>>>();
    prep_kernel<<<dim3(NROWS * DDIM / 4 / 256, 3), 256>>>(m0, m1, m2);
    sqnorm_kernel<<<(3 * NROWS * 32) / 256, 256>>>(m0, m1, m2);
    gram_mma<<<dim3(32, 64, 6), 256>>>();
    finish_kernel<<<1, 1>>>(out);
}

// round 5
// speedup vs baseline: 14.0311x; 1.1913x over previous
#include <cuda_runtime.h>
#include <cuda_bf16.h>
#include <math.h>
#include <stdint.h>

#define NROWS 8192
#define DDIM  64
#define KSIZE 128.0
#define SIGMA 3.0
#define EPSV  1e-5

// ---------------------------------------------------------------------------
// Device-global scratch (no allocation allowed in kernel_launch)
// ---------------------------------------------------------------------------
__device__ double g_sums[6];
__device__ float  g_rl[3 * NROWS];                              // -|x|^2/(128 ln2)
__device__ __align__(16) __nv_bfloat16 g_bf[3 * NROWS * DDIM];  // bf16 copies

// ---------------------------------------------------------------------------
static __device__ __forceinline__ uint32_t smem_u32(const void* p) {
    uint32_t a;
    asm("{ .reg .u64 t; cvta.to.shared.u64 t, %1; cvt.u32.u64 %0, t; }"
        : "=r"(a) : "l"(p));
    return a;
}
static __device__ __forceinline__ float ex2f(float x) {
    float r; asm("ex2.approx.ftz.f32 %0, %1;" : "=f"(r) : "f"(x)); return r;
}
static __device__ __forceinline__ void ldsm_x4(uint32_t* r, uint32_t addr) {
    asm volatile("ldmatrix.sync.aligned.m8n8.x4.shared.b16 {%0,%1,%2,%3}, [%4];"
                 : "=r"(r[0]), "=r"(r[1]), "=r"(r[2]), "=r"(r[3]) : "r"(addr));
}
static __device__ __forceinline__ void mma16816(float* d, const uint32_t* a,
                                                uint32_t b0, uint32_t b1) {
    asm volatile(
        "mma.sync.aligned.m16n8k16.row.col.f32.bf16.bf16.f32 "
        "{%0,%1,%2,%3}, {%4,%5,%6,%7}, {%8,%9}, {%0,%1,%2,%3};"
        : "+f"(d[0]), "+f"(d[1]), "+f"(d[2]), "+f"(d[3])
        : "r"(a[0]), "r"(a[1]), "r"(a[2]), "r"(a[3]), "r"(b0), "r"(b1));
}
static __device__ __forceinline__ void cp16(uint32_t dst, const void* src) {
    asm volatile("cp.async.cg.shared.global [%0], [%1], 16;" :: "r"(dst), "l"(src));
}
#define CP_COMMIT() asm volatile("cp.async.commit_group;" ::: "memory")
#define CP_WAIT(n)  asm volatile("cp.async.wait_group %0;" :: "n"(n) : "memory")

// ---------------------------------------------------------------------------
// Aux kernels
// ---------------------------------------------------------------------------
__global__ void init_kernel() {
    if (threadIdx.x < 6) g_sums[threadIdx.x] = 0.0;
}

__global__ void prep_kernel(const float* __restrict__ m0,
                            const float* __restrict__ m1,
                            const float* __restrict__ m2) {
    int i = blockIdx.x * blockDim.x + threadIdx.x;   // over NROWS*DDIM/4
    int mod = blockIdx.y;
    const float* src = (mod == 0) ? m0 : (mod == 1) ? m1 : m2;
    float4 v = ((const float4*)src)[i];
    __nv_bfloat162* dst = (__nv_bfloat162*)(g_bf + (size_t)mod * NROWS * DDIM);
    dst[2 * i]     = __float22bfloat162_rn(make_float2(v.x, v.y));
    dst[2 * i + 1] = __float22bfloat162_rn(make_float2(v.z, v.w));
}

__global__ void sqnorm_kernel(const float* __restrict__ m0,
                              const float* __restrict__ m1,
                              const float* __restrict__ m2) {
    int warp = (blockIdx.x * blockDim.x + threadIdx.x) >> 5;
    int lane = threadIdx.x & 31;
    if (warp >= 3 * NROWS) return;
    int mod = warp / NROWS;
    int row = warp - mod * NROWS;
    const float* p = (mod == 0) ? m0 : (mod == 1) ? m1 : m2;
    float2 v = ((const float2*)(p + (size_t)row * DDIM))[lane];
    float s = v.x * v.x + v.y * v.y;
    #pragma unroll
    for (int off = 16; off > 0; off >>= 1)
        s += __shfl_down_sync(0xffffffffu, s, off);
    if (lane == 0) g_rl[warp] = s * (float)(-1.0 / (128.0 * M_LN2));
}

// ---------------------------------------------------------------------------
// One 64x32 warp tile vs K=64 from swizzled smem + exp epilogue.
// A tile has 128 rows in smem, B tile has 64 rows.
// ---------------------------------------------------------------------------
static __device__ __forceinline__ float tile_compute(
    uint32_t baseA, uint32_t baseB, const float* ra,
    const float* __restrict__ rlB, float lw,
    int lane, int warp_m, int warp_n)
{
    const int tig = lane & 3;
    const int a_r  = lane & 15;
    const int a_kh = lane >> 4;
    const int b_r  = (lane & 7) + ((lane & 16) >> 1);
    const int b_kh = (lane >> 3) & 1;

    float d[4][4][4];
    #pragma unroll
    for (int mf = 0; mf < 4; mf++)
        #pragma unroll
        for (int nf = 0; nf < 4; nf++)
            #pragma unroll
            for (int q = 0; q < 4; q++) d[mf][nf][q] = 0.0f;

    #pragma unroll
    for (int ks = 0; ks < 4; ks++) {
        uint32_t a[4][4];
        #pragma unroll
        for (int mf = 0; mf < 4; mf++) {
            int row = warp_m + mf * 16 + a_r;
            int kc = ks * 2 + a_kh;
            ldsm_x4(a[mf], baseA + row * 128 + ((kc ^ (row & 7)) << 4));
        }
        uint32_t b[2][4];
        #pragma unroll
        for (int bf = 0; bf < 2; bf++) {
            int row = warp_n + bf * 16 + b_r;
            int kc = ks * 2 + b_kh;
            ldsm_x4(b[bf], baseB + row * 128 + ((kc ^ (row & 7)) << 4));
        }
        #pragma unroll
        for (int mf = 0; mf < 4; mf++)
            #pragma unroll
            for (int nf = 0; nf < 4; nf++)
                mma16816(d[mf][nf], a[mf],
                         b[nf >> 1][(nf & 1) * 2], b[nf >> 1][(nf & 1) * 2 + 1]);
    }

    // pb = 2^(rb + lw); K(i,j) = 2^(d*C2 + ra) * pb
    const float C2 = (float)(1.0 / (64.0 * M_LN2));
    float pb[4][2];
    #pragma unroll
    for (int nf = 0; nf < 4; nf++) {
        pb[nf][0] = ex2f(rlB[nf * 8 + tig * 2] + lw);
        pb[nf][1] = ex2f(rlB[nf * 8 + tig * 2 + 1] + lw);
    }

    float s0 = 0.0f, s1 = 0.0f, s2 = 0.0f, s3 = 0.0f;
    #pragma unroll
    for (int mf = 0; mf < 4; mf++)
        #pragma unroll
        for (int nf = 0; nf < 4; nf++) {
            s0 = fmaf(ex2f(fmaf(d[mf][nf][0], C2, ra[2 * mf])),     pb[nf][0], s0);
            s1 = fmaf(ex2f(fmaf(d[mf][nf][1], C2, ra[2 * mf])),     pb[nf][1], s1);
            s2 = fmaf(ex2f(fmaf(d[mf][nf][2], C2, ra[2 * mf + 1])), pb[nf][0], s2);
            s3 = fmaf(ex2f(fmaf(d[mf][nf][3], C2, ra[2 * mf + 1])), pb[nf][1], s3);
        }
    return (s0 + s1) + (s2 + s3);
}

// ---------------------------------------------------------------------------
// Main Gram kernel. 128-thread CTAs, 4 resident per SM (phase decorrelation).
// grid = (32, 64, 6): bjs (4 x 64-col subtiles = 256 cols), bi (128 rows), pair.
// CTA tile 128x64, 4 warps in 2x2 of 64x32 warp tiles. A loaded once; B tiles
// (8 KB) rolling double-buffered via cp.async. Symmetric pairs handled at
// 64-col granularity: jj < 2bi skip, jj in {2bi,2bi+1} weight 1, else weight 2.
// ---------------------------------------------------------------------------
__global__ __launch_bounds__(128, 4) void gram_mma() {
    const int pz = blockIdx.z;
    const int pa_[6] = {0, 1, 2, 0, 0, 1};
    const int pb_[6] = {0, 1, 2, 1, 2, 2};
    const int ia = pa_[pz], ib = pb_[pz];
    const int bi = blockIdx.y, bjs = blockIdx.x;
    const int jj0 = 4 * bjs;
    const bool sym = (pz < 3);
    if (sym && jj0 + 3 < 2 * bi) return;

    __shared__ __align__(128) uint4 smA[1024];      // 128 rows x 8 chunks, 16 KB
    __shared__ __align__(128) uint4 smB[2][512];    // 2 x (64 rows), 8 KB each
    __shared__ float red[4];

    const int tid = threadIdx.x;
    const int wid = tid >> 5, lane = tid & 31;

    const uint4* Ag = (const uint4*)(g_bf + (size_t)ia * NROWS * DDIM) + (size_t)bi * 1024;
    const uint4* Bbase = (const uint4*)(g_bf + (size_t)ib * NROWS * DDIM);

    const uint32_t baseA = smem_u32(smA);
    uint32_t baseB[2] = { smem_u32(smB[0]), smem_u32(smB[1]) };

    // Group 0: A + B(jj0); Group 1: B(jj0+1)
    #pragma unroll
    for (int q = 0; q < 8; q++) {
        int c = tid + 128 * q;
        int row = c >> 3, kc = c & 7;
        cp16(baseA + (uint32_t)(row * 8 + (kc ^ (row & 7))) * 16u, Ag + c);
    }
    #pragma unroll
    for (int q = 0; q < 4; q++) {
        int c = tid + 128 * q;
        int row = c >> 3, kc = c & 7;
        cp16(baseB[0] + (uint32_t)(row * 8 + (kc ^ (row & 7))) * 16u,
             Bbase + (size_t)jj0 * 512 + c);
    }
    CP_COMMIT();
    #pragma unroll
    for (int q = 0; q < 4; q++) {
        int c = tid + 128 * q;
        int row = c >> 3, kc = c & 7;
        cp16(baseB[1] + (uint32_t)(row * 8 + (kc ^ (row & 7))) * 16u,
             Bbase + (size_t)(jj0 + 1) * 512 + c);
    }
    CP_COMMIT();

    // Per-thread A-row exponent terms
    const int warp_m = (wid & 1) * 64;
    const int warp_n = (wid >> 1) * 32;
    const int g = lane >> 2;
    const float* rlA = g_rl + ia * NROWS + bi * 128 + warp_m;
    float ra[8];
    #pragma unroll
    for (int mf = 0; mf < 4; mf++) {
        ra[2 * mf]     = rlA[mf * 16 + g];
        ra[2 * mf + 1] = rlA[mf * 16 + g + 8];
    }

    float s = 0.0f;

    #pragma unroll
    for (int t = 0; t < 4; t++) {
        const int jj = jj0 + t;
        CP_WAIT(1);                 // B(t) resident (B(t+1) may be in flight)
        __syncthreads();
        if (!(sym && jj < 2 * bi)) {
            const float lw = (sym && jj > 2 * bi + 1) ? 1.0f : 0.0f;
            s += tile_compute(baseA, baseB[t & 1], ra,
                              g_rl + ib * NROWS + jj * 64 + warp_n, lw,
                              lane, warp_m, warp_n);
        }
        __syncthreads();            // everyone done reading buf[t&1]
        if (t + 2 < 4) {
            #pragma unroll
            for (int q = 0; q < 4; q++) {
                int c = tid + 128 * q;
                int row = c >> 3, kc = c & 7;
                cp16(baseB[t & 1] + (uint32_t)(row * 8 + (kc ^ (row & 7))) * 16u,
                     Bbase + (size_t)(jj0 + t + 2) * 512 + c);
            }
        }
        CP_COMMIT();                // empty groups keep the wait count uniform
    }

    // Block reduce -> one double atomic per CTA
    #pragma unroll
    for (int off = 16; off > 0; off >>= 1)
        s += __shfl_down_sync(0xffffffffu, s, off);
    if (lane == 0) red[wid] = s;
    __syncthreads();
    if (tid == 0) {
        float bs = (red[0] + red[1]) + (red[2] + red[3]);
        atomicAdd(&g_sums[pz], (double)bs);
    }
}

// ---------------------------------------------------------------------------
// Epilogue: 3 log-ratio terms in double
// ---------------------------------------------------------------------------
__global__ void finish_kernel(float* __restrict__ out) {
    const double norm = sqrt(2.0 * M_PI * KSIZE);
    const double inv  = 1.0 / ((double)NROWS * (double)NROWS * norm);
    double m[6];
    #pragma unroll
    for (int q = 0; q < 6; q++) m[q] = g_sums[q] * inv;
    double loss = 0.0;
    loss += log(SIGMA * sqrt(m[0] * m[1] + EPSV) / (m[3] + EPSV));
    loss += log(SIGMA * sqrt(m[0] * m[2] + EPSV) / (m[4] + EPSV));
    loss += log(SIGMA * sqrt(m[1] * m[2] + EPSV) / (m[5] + EPSV));
    out[0] = (float)loss;
}

// ---------------------------------------------------------------------------
extern "C" void kernel_launch(void* const* d_in, const int* in_sizes, int n_in,
                              void* d_out, int out_size) {
    const float* m0 = (const float*)d_in[0];
    const float* m1 = (const float*)d_in[1];
    const float* m2 = (const float*)d_in[2];
    float* out = (float*)d_out;

    init_kernel<<<1, 32>>>();
    prep_kernel<<<dim3(NROWS * DDIM / 4 / 256, 3), 256>>>(m0, m1, m2);
    sqnorm_kernel<<<(3 * NROWS * 32) / 256, 256>>>(m0, m1, m2);
    gram_mma<<<dim3(32, 64, 6), 128>>>();
    finish_kernel<<<1, 1>>>(out);
}

// round 6
// speedup vs baseline: 14.0924x; 1.0044x over previous
#include <cuda_runtime.h>
#include <cuda_bf16.h>
#include <math.h>
#include <stdint.h>

#define NROWS 8192
#define DDIM  64
#define KSIZE 128.0
#define SIGMA 3.0
#define EPSV  1e-5

// ---------------------------------------------------------------------------
// Device-global scratch (no allocation allowed in kernel_launch)
// ---------------------------------------------------------------------------
__device__ double g_sums[6];
__device__ float  g_rl[3 * NROWS];                              // -|x|^2/(128 ln2)
__device__ __align__(16) __nv_bfloat16 g_bf[3 * NROWS * DDIM];  // bf16 copies

// ---------------------------------------------------------------------------
static __device__ __forceinline__ uint32_t smem_u32(const void* p) {
    uint32_t a;
    asm("{ .reg .u64 t; cvta.to.shared.u64 t, %1; cvt.u32.u64 %0, t; }"
        : "=r"(a) : "l"(p));
    return a;
}
static __device__ __forceinline__ float ex2f(float x) {
    float r; asm("ex2.approx.ftz.f32 %0, %1;" : "=f"(r) : "f"(x)); return r;
}
static __device__ __forceinline__ void ldsm_x4(uint32_t* r, uint32_t addr) {
    asm volatile("ldmatrix.sync.aligned.m8n8.x4.shared.b16 {%0,%1,%2,%3}, [%4];"
                 : "=r"(r[0]), "=r"(r[1]), "=r"(r[2]), "=r"(r[3]) : "r"(addr));
}
static __device__ __forceinline__ void mma16816(float* d, const uint32_t* a,
                                                uint32_t b0, uint32_t b1) {
    asm volatile(
        "mma.sync.aligned.m16n8k16.row.col.f32.bf16.bf16.f32 "
        "{%0,%1,%2,%3}, {%4,%5,%6,%7}, {%8,%9}, {%0,%1,%2,%3};"
        : "+f"(d[0]), "+f"(d[1]), "+f"(d[2]), "+f"(d[3])
        : "r"(a[0]), "r"(a[1]), "r"(a[2]), "r"(a[3]), "r"(b0), "r"(b1));
}
static __device__ __forceinline__ void cp16(uint32_t dst, const void* src) {
    asm volatile("cp.async.cg.shared.global [%0], [%1], 16;" :: "r"(dst), "l"(src));
}
#define CP_COMMIT() asm volatile("cp.async.commit_group;" ::: "memory")
#define CP_WAIT(n)  asm volatile("cp.async.wait_group %0;" :: "n"(n) : "memory")

// ---------------------------------------------------------------------------
// Fused prep: bf16 convert + row norms (+ zero the 6 accumulators).
// One warp per row; 8 warps per block.
// ---------------------------------------------------------------------------
__global__ void fused_prep(const float* __restrict__ m0,
                           const float* __restrict__ m1,
                           const float* __restrict__ m2) {
    const int tid = threadIdx.x;
    if (blockIdx.x == 0 && tid < 6) g_sums[tid] = 0.0;

    const int gw   = blockIdx.x * 8 + (tid >> 5);   // global warp = row id
    const int lane = tid & 31;
    if (gw >= 3 * NROWS) return;
    const int mod = gw / NROWS;
    const int row = gw - mod * NROWS;
    const float* src = (mod == 0) ? m0 : (mod == 1) ? m1 : m2;

    float2 v = ((const float2*)(src + (size_t)row * DDIM))[lane];
    __nv_bfloat162* dst = (__nv_bfloat162*)(g_bf + (size_t)gw * DDIM);
    dst[lane] = __float22bfloat162_rn(v);

    float s = v.x * v.x + v.y * v.y;
    #pragma unroll
    for (int off = 16; off > 0; off >>= 1)
        s += __shfl_down_sync(0xffffffffu, s, off);
    if (lane == 0) g_rl[gw] = s * (float)(-1.0 / (128.0 * M_LN2));
}

// ---------------------------------------------------------------------------
// One 64x32 warp tile vs K=64: A (64 rows) in shared smem, B (32 rows) in the
// warp's private smem slice. Returns this thread's partial kernel-sum.
// ---------------------------------------------------------------------------
static __device__ __forceinline__ float tile_compute(
    uint32_t baseA, uint32_t baseB, const float* ra,
    const float* __restrict__ rlB, float lw, int lane)
{
    const int tig  = lane & 3;
    const int a_r  = lane & 15;
    const int a_kh = lane >> 4;
    const int b_r  = (lane & 7) + ((lane & 16) >> 1);
    const int b_kh = (lane >> 3) & 1;

    float d[4][4][4];
    #pragma unroll
    for (int mf = 0; mf < 4; mf++)
        #pragma unroll
        for (int nf = 0; nf < 4; nf++)
            #pragma unroll
            for (int q = 0; q < 4; q++) d[mf][nf][q] = 0.0f;

    #pragma unroll
    for (int ks = 0; ks < 4; ks++) {
        uint32_t a[4][4];
        #pragma unroll
        for (int mf = 0; mf < 4; mf++) {
            int row = mf * 16 + a_r;
            int kc = ks * 2 + a_kh;
            ldsm_x4(a[mf], baseA + row * 128 + ((kc ^ (row & 7)) << 4));
        }
        uint32_t b[2][4];
        #pragma unroll
        for (int bf = 0; bf < 2; bf++) {
            int row = bf * 16 + b_r;
            int kc = ks * 2 + b_kh;
            ldsm_x4(b[bf], baseB + row * 128 + ((kc ^ (row & 7)) << 4));
        }
        #pragma unroll
        for (int mf = 0; mf < 4; mf++)
            #pragma unroll
            for (int nf = 0; nf < 4; nf++)
                mma16816(d[mf][nf], a[mf],
                         b[nf >> 1][(nf & 1) * 2], b[nf >> 1][(nf & 1) * 2 + 1]);
    }

    const float C2 = (float)(1.0 / (64.0 * M_LN2));
    float pb[4][2];
    #pragma unroll
    for (int nf = 0; nf < 4; nf++) {
        pb[nf][0] = ex2f(rlB[nf * 8 + tig * 2] + lw);
        pb[nf][1] = ex2f(rlB[nf * 8 + tig * 2 + 1] + lw);
    }

    float s0 = 0.0f, s1 = 0.0f, s2 = 0.0f, s3 = 0.0f;
    #pragma unroll
    for (int mf = 0; mf < 4; mf++)
        #pragma unroll
        for (int nf = 0; nf < 4; nf++) {
            s0 = fmaf(ex2f(fmaf(d[mf][nf][0], C2, ra[2 * mf])),     pb[nf][0], s0);
            s1 = fmaf(ex2f(fmaf(d[mf][nf][1], C2, ra[2 * mf])),     pb[nf][1], s1);
            s2 = fmaf(ex2f(fmaf(d[mf][nf][2], C2, ra[2 * mf + 1])), pb[nf][0], s2);
            s3 = fmaf(ex2f(fmaf(d[mf][nf][3], C2, ra[2 * mf + 1])), pb[nf][1], s3);
        }
    return (s0 + s1) + (s2 + s3);
}

// ---------------------------------------------------------------------------
// Main Gram kernel: per-warp independent pipelines, no block sync in mainloop.
// grid = (16, 128, 6): bjs (16 x 32-col slices = 512 cols), bi (64 rows), pair.
// CTA = 4 warps; A (64 rows, 8 KB) shared, loaded once. Each warp owns 4
// consecutive 32-col B slices, double-buffered in private smem via its own
// cp.async groups (wait_group + syncwarp only).
// Symmetric pairs at 32-col granularity: j < 2bi skip, j in {2bi, 2bi+1}
// weight 1, j > 2bi+1 weight 2 (folded as +1 in the log2 exponent).
// ---------------------------------------------------------------------------
__global__ __launch_bounds__(128, 4) void gram_mma() {
    const int pz = blockIdx.z;
    const int pa_[6] = {0, 1, 2, 0, 0, 1};
    const int pb_[6] = {0, 1, 2, 1, 2, 2};
    const int ia = pa_[pz], ib = pb_[pz];
    const int bi = blockIdx.y, bjs = blockIdx.x;
    const bool sym = (pz < 3);
    if (sym && bjs * 16 + 15 < 2 * bi) return;       // whole CTA below diagonal

    __shared__ __align__(128) uint4 smA[512];        // 64 rows x 8 chunks, 8 KB
    __shared__ __align__(128) uint4 smB[4][2][256];  // per-warp double buffer

    const int tid = threadIdx.x;
    const int wid = tid >> 5, lane = tid & 31;
    const int j0 = bjs * 16 + wid * 4;               // this warp's first slice

    const uint4* Ag = (const uint4*)(g_bf + (size_t)ia * NROWS * DDIM) + (size_t)bi * 512;
    const uint4* Bbase = (const uint4*)(g_bf + (size_t)ib * NROWS * DDIM);

    const uint32_t baseA = smem_u32(smA);
    const uint32_t baseB[2] = { smem_u32(smB[wid][0]), smem_u32(smB[wid][1]) };

    // --- Prologue ---------------------------------------------------------
    // Group 0: A (cooperative) + this warp's B slice 0. Group 1: B slice 1.
    #pragma unroll
    for (int q = 0; q < 4; q++) {
        int c = tid + 128 * q;
        int row = c >> 3, kc = c & 7;
        cp16(baseA + (uint32_t)(row * 8 + (kc ^ (row & 7))) * 16u, Ag + c);
    }
    #pragma unroll
    for (int t0 = 0; t0 < 2; t0++) {
        int j = j0 + t0;
        if (!(sym && j < 2 * bi)) {
            #pragma unroll
            for (int q = 0; q < 8; q++) {
                int c = lane + 32 * q;
                int row = c >> 3, kc = c & 7;
                cp16(baseB[t0] + (uint32_t)(row * 8 + (kc ^ (row & 7))) * 16u,
                     Bbase + (size_t)j * 256 + c);
            }
        }
        CP_COMMIT();
    }

    // Per-thread A-row exponent terms
    const int g = lane >> 2;
    const float* rlA = g_rl + ia * NROWS + bi * 64;
    float ra[8];
    #pragma unroll
    for (int mf = 0; mf < 4; mf++) {
        ra[2 * mf]     = rlA[mf * 16 + g];
        ra[2 * mf + 1] = rlA[mf * 16 + g + 8];
    }

    float s = 0.0f;

    // --- Mainloop: warp-private, no block sync ----------------------------
    #pragma unroll
    for (int t = 0; t < 4; t++) {
        const int j = j0 + t;
        CP_WAIT(1);                     // group t complete (t+1 may be pending)
        if (t == 0) __syncthreads();    // A visible CTA-wide (once)
        else        __syncwarp();
        if (!(sym && j < 2 * bi)) {
            const float lw = (sym && j > 2 * bi + 1) ? 1.0f : 0.0f;
            s += tile_compute(baseA, baseB[t & 1], ra,
                              g_rl + ib * NROWS + j * 32, lw, lane);
        }
        if (t < 2) {                    // prefetch slice t+2 into buf[t&1]
            int jn = j0 + t + 2;
            if (!(sym && jn < 2 * bi)) {
                #pragma unroll
                for (int q = 0; q < 8; q++) {
                    int c = lane + 32 * q;
                    int row = c >> 3, kc = c & 7;
                    cp16(baseB[t & 1] + (uint32_t)(row * 8 + (kc ^ (row & 7))) * 16u,
                         Bbase + (size_t)jn * 256 + c);
                }
            }
        }
        CP_COMMIT();                    // uniform group count (may be empty)
    }

    // Warp reduce -> one double atomic per warp
    #pragma unroll
    for (int off = 16; off > 0; off >>= 1)
        s += __shfl_down_sync(0xffffffffu, s, off);
    if (lane == 0)
        atomicAdd(&g_sums[pz], (double)s);
}

// ---------------------------------------------------------------------------
// Epilogue: 3 log-ratio terms in double
// ---------------------------------------------------------------------------
__global__ void finish_kernel(float* __restrict__ out) {
    const double norm = sqrt(2.0 * M_PI * KSIZE);
    const double inv  = 1.0 / ((double)NROWS * (double)NROWS * norm);
    double m[6];
    #pragma unroll
    for (int q = 0; q < 6; q++) m[q] = g_sums[q] * inv;
    double loss = 0.0;
    loss += log(SIGMA * sqrt(m[0] * m[1] + EPSV) / (m[3] + EPSV));
    loss += log(SIGMA * sqrt(m[0] * m[2] + EPSV) / (m[4] + EPSV));
    loss += log(SIGMA * sqrt(m[1] * m[2] + EPSV) / (m[5] + EPSV));
    out[0] = (float)loss;
}

// ---------------------------------------------------------------------------
extern "C" void kernel_launch(void* const* d_in, const int* in_sizes, int n_in,
                              void* d_out, int out_size) {
    const float* m0 = (const float*)d_in[0];
    const float* m1 = (const float*)d_in[1];
    const float* m2 = (const float*)d_in[2];
    float* out = (float*)d_out;

    fused_prep<<<(3 * NROWS) / 8, 256>>>(m0, m1, m2);
    gram_mma<<<dim3(16, 128, 6), 128>>>();
    finish_kernel<<<1, 1>>>(out);
}